// round 2
// baseline (speedup 1.0000x reference)
#include <cuda_runtime.h>

#define MAXN 100000
#define MAXE 1600000
#define MAXT (MAXE + MAXN)

// ---------------- scratch (static device globals; no runtime allocation) ----------------
__device__ __align__(16) float g_h[(size_t)MAXN * 128];   // per-layer h = x @ W
__device__ __align__(16) float g_x[(size_t)MAXN * 128];   // activations between layers
__device__ float g_as[MAXN];
__device__ float g_ad[MAXN];
__device__ int   g_deg[MAXN];
__device__ int   g_off[MAXN + 1];
__device__ int   g_cur[MAXN];
__device__ int   g_srcs[MAXT];
__device__ int   g_is64;      // 1 if adj is int64, 0 if int32

// ---------------- adjacency dtype detection ----------------
// If adj is int64 (little-endian, values < 2^31), odd int32 words are all 0.
__global__ void detect_kernel(const int* __restrict__ w) {
    if (threadIdx.x == 0) {
        int all0 = 1;
        #pragma unroll 1
        for (int i = 0; i < 64; i++)
            if (w[2 * i + 1] != 0) { all0 = 0; break; }
        g_is64 = all0;
    }
}

__device__ __forceinline__ int fetch_idx(const int* __restrict__ p, int i, int is64) {
    return is64 ? p[2 * i] : p[i];
}

// ---------------- CSR build (by destination; shared across all 3 layers) ----------------
__global__ void init_deg_kernel(int n) {
    int i = blockIdx.x * blockDim.x + threadIdx.x;
    if (i < n) g_deg[i] = 1;  // self-loop per node
}

__global__ void count_kernel(const int* __restrict__ dst, int e) {
    int i = blockIdx.x * blockDim.x + threadIdx.x;
    int is64 = g_is64;
    if (i < e) atomicAdd(&g_deg[fetch_idx(dst, i, is64)], 1);
}

// single-block exclusive scan: 1024 threads, each owning a contiguous chunk
__global__ void scan_kernel(int n) {
    __shared__ int sh[1024];
    int t = threadIdx.x;
    int chunk = (n + 1023) >> 10;
    int lo = t * chunk;
    int hi = min(n, lo + chunk);
    int local = 0;
    for (int i = lo; i < hi; i++) local += g_deg[i];
    sh[t] = local;
    __syncthreads();
    #pragma unroll 1
    for (int d = 1; d < 1024; d <<= 1) {
        int v = (t >= d) ? sh[t - d] : 0;
        __syncthreads();
        sh[t] += v;
        __syncthreads();
    }
    int run = sh[t] - local;  // exclusive prefix of this chunk
    for (int i = lo; i < hi; i++) { g_off[i] = run; run += g_deg[i]; }
    if (t == 1023) g_off[n] = sh[1023];
}

__global__ void cursor_kernel(int n) {
    int i = blockIdx.x * blockDim.x + threadIdx.x;
    if (i < n) g_cur[i] = g_off[i];
}

__global__ void scatter_kernel(const int* __restrict__ src,
                               const int* __restrict__ dst, int e, int n) {
    int i = blockIdx.x * blockDim.x + threadIdx.x;
    int is64 = g_is64;
    if (i < e) {
        int d = fetch_idx(dst, i, is64);
        int p = atomicAdd(&g_cur[d], 1);
        g_srcs[p] = fetch_idx(src, i, is64);
    } else if (i < e + n) {
        int v = i - e;                      // self-loop
        int p = atomicAdd(&g_cur[v], 1);
        g_srcs[p] = v;
    }
}

// ---------------- SGEMM: C(g_h)[M,Nc] = A[M,K] @ B[K,Nc], fp32, 128x64 tile ----------------
template <bool FROM_GX>
__global__ void __launch_bounds__(256)
sgemm_kernel(const float* __restrict__ Ain, const float* __restrict__ Bw,
             int M, int K, int Nc) {
    constexpr int BM = 128, BN = 64, BK = 16, TM = 8, TN = 4;
    __shared__ float As[BK][BM];
    __shared__ float Bs[BK][BN];
    const float* A = FROM_GX ? g_x : Ain;
    int tid = threadIdx.x;
    int tr = tid >> 4;          // 0..15 (M direction)
    int tc = tid & 15;          // 0..15 (N direction)
    int rowBase = blockIdx.x * BM;
    int colBase = blockIdx.y * BN;
    int aRow = tid >> 2;        // 0..63
    int aCol = (tid & 3) * 4;   // 0,4,8,12 within BK
    int bRow = tid >> 4;        // 0..15 (BK)
    int bCol = (tid & 15) * 4;  // float4 within BN

    float acc[TM][TN];
    #pragma unroll
    for (int i = 0; i < TM; i++)
        #pragma unroll
        for (int j = 0; j < TN; j++) acc[i][j] = 0.f;

    for (int k0 = 0; k0 < K; k0 += BK) {
        #pragma unroll
        for (int half = 0; half < 2; half++) {
            int r = aRow + half * 64;
            int gr = rowBase + r;
            float4 v = make_float4(0.f, 0.f, 0.f, 0.f);
            if (gr < M)
                v = *reinterpret_cast<const float4*>(&A[(size_t)gr * K + k0 + aCol]);
            As[aCol + 0][r] = v.x;
            As[aCol + 1][r] = v.y;
            As[aCol + 2][r] = v.z;
            As[aCol + 3][r] = v.w;
        }
        *reinterpret_cast<float4*>(&Bs[bRow][bCol]) =
            *reinterpret_cast<const float4*>(&Bw[(size_t)(k0 + bRow) * Nc + colBase + bCol]);
        __syncthreads();
        #pragma unroll
        for (int kk = 0; kk < BK; kk++) {
            float af[TM], bf[TN];
            *reinterpret_cast<float4*>(&af[0]) =
                *reinterpret_cast<const float4*>(&As[kk][tr * TM]);
            *reinterpret_cast<float4*>(&af[4]) =
                *reinterpret_cast<const float4*>(&As[kk][tr * TM + 4]);
            *reinterpret_cast<float4*>(&bf[0]) =
                *reinterpret_cast<const float4*>(&Bs[kk][tc * TN]);
            #pragma unroll
            for (int i = 0; i < TM; i++)
                #pragma unroll
                for (int j = 0; j < TN; j++)
                    acc[i][j] = fmaf(af[i], bf[j], acc[i][j]);
        }
        __syncthreads();
    }
    #pragma unroll
    for (int i = 0; i < TM; i++) {
        int gr = rowBase + tr * TM + i;
        if (gr < M) {
            float4 v = make_float4(acc[i][0], acc[i][1], acc[i][2], acc[i][3]);
            *reinterpret_cast<float4*>(&g_h[(size_t)gr * Nc + colBase + tc * TN]) = v;
        }
    }
}

// ---------------- per-node attention dots: as = h.a_src, ad = h.a_dst ----------------
template <int DO>
__global__ void alpha_kernel(const float* __restrict__ a_src,
                             const float* __restrict__ a_dst, int n) {
    constexpr int VEC = DO / 32;
    int w = (blockIdx.x * blockDim.x + threadIdx.x) >> 5;
    int lane = threadIdx.x & 31;
    if (w >= n) return;
    float s = 0.f, d = 0.f;
    const float* hp = &g_h[(size_t)w * DO + lane * VEC];
    #pragma unroll
    for (int k = 0; k < VEC; k++) {
        float hv = hp[k];
        s = fmaf(hv, a_src[lane * VEC + k], s);
        d = fmaf(hv, a_dst[lane * VEC + k], d);
    }
    #pragma unroll
    for (int o = 16; o; o >>= 1) {
        s += __shfl_xor_sync(0xffffffffu, s, o);
        d += __shfl_xor_sync(0xffffffffu, d, o);
    }
    if (lane == 0) { g_as[w] = s; g_ad[w] = d; }
}

// ---------------- per-dst segment softmax + weighted feature aggregation ----------------
// one warp per destination node; two passes over its CSR row
template <int DO, bool TO_GX>
__global__ void aggregate_kernel(const float* __restrict__ bias,
                                 float* __restrict__ outp, int n) {
    constexpr int VEC = DO / 32;
    int node = (blockIdx.x * blockDim.x + threadIdx.x) >> 5;
    int lane = threadIdx.x & 31;
    if (node >= n) return;
    int s0 = g_off[node], s1 = g_off[node + 1];
    float adn = g_ad[node];

    // pass A: row max of leaky(logit)
    float m = -1e30f;
    for (int j = s0 + lane; j < s1; j += 32) {
        float v = g_as[g_srcs[j]] + adn;
        v = v > 0.f ? v : 0.2f * v;
        m = fmaxf(m, v);
    }
    #pragma unroll
    for (int o = 16; o; o >>= 1) m = fmaxf(m, __shfl_xor_sync(0xffffffffu, m, o));

    // pass B: exp-weights + coalesced gather of h[src]
    float acc[VEC];
    #pragma unroll
    for (int k = 0; k < VEC; k++) acc[k] = 0.f;
    float ssum = 0.f;
    for (int j = s0; j < s1; ++j) {
        int s = g_srcs[j];               // broadcast load (same addr all lanes)
        float v = g_as[s] + adn;
        v = v > 0.f ? v : 0.2f * v;
        float w = __expf(v - m);
        ssum += w;
        const float* hp = &g_h[(size_t)s * DO + lane * VEC];
        if constexpr (VEC == 4) {
            float4 hv = *reinterpret_cast<const float4*>(hp);
            acc[0] = fmaf(w, hv.x, acc[0]);
            acc[1] = fmaf(w, hv.y, acc[1]);
            acc[2] = fmaf(w, hv.z, acc[2]);
            acc[3] = fmaf(w, hv.w, acc[3]);
        } else {
            float2 hv = *reinterpret_cast<const float2*>(hp);
            acc[0] = fmaf(w, hv.x, acc[0]);
            acc[1] = fmaf(w, hv.y, acc[1]);
        }
    }
    float inv = 1.f / ssum;
    #pragma unroll
    for (int k = 0; k < VEC; k++) {
        float o = fmaf(acc[k], inv, bias[lane * VEC + k]);
        acc[k] = o > 0.f ? o : 0.25f * o;   // outer leaky_relu(0.25)
    }
    float* op = TO_GX ? &g_x[(size_t)node * DO + lane * VEC]
                      : &outp[(size_t)node * DO + lane * VEC];
    if constexpr (VEC == 4)
        *reinterpret_cast<float4*>(op) = make_float4(acc[0], acc[1], acc[2], acc[3]);
    else
        *reinterpret_cast<float2*>(op) = make_float2(acc[0], acc[1]);
}

// ---------------- launch ----------------
extern "C" void kernel_launch(void* const* d_in, const int* in_sizes, int n_in,
                              void* d_out, int out_size) {
    const float* data = (const float*)d_in[0];
    const int*   adj  = (const int*)d_in[1];   // int32 words; dtype detected on device
    const float* W1  = (const float*)d_in[2];
    const float* as1 = (const float*)d_in[3];
    const float* ad1 = (const float*)d_in[4];
    const float* b1  = (const float*)d_in[5];
    const float* W2  = (const float*)d_in[6];
    const float* as2 = (const float*)d_in[7];
    const float* ad2 = (const float*)d_in[8];
    const float* b2  = (const float*)d_in[9];
    const float* W3  = (const float*)d_in[10];
    const float* as3 = (const float*)d_in[11];
    const float* ad3 = (const float*)d_in[12];
    const float* b3  = (const float*)d_in[13];

    int Nn = in_sizes[0] / 512;
    int Ee = in_sizes[1] / 2;   // element count (dtype-agnostic)

    const int T = 256;
    int warpGrid = (Nn * 32 + T - 1) / T;

    detect_kernel<<<1, 32>>>(adj);

    // src/dst word offsets depend on dtype; pass base pointers offset on device side:
    // For int32: src = adj[0..E), dst = adj[E..2E).
    // For int64: src words = adj[0..2E), dst words = adj[2E..4E); fetch uses 2*i.
    // We pass dst base as adj + Ee (int32) — for int64 the dst base is adj + 2*Ee words.
    // Handle by passing both and selecting inside via g_is64: simplest is to pass
    // adj and compute the dst offset inside the kernels. We do that via pointer math here:
    // count/scatter take src base = adj, dst base = adj + Ee (int32) or adj + 2*Ee (int64).
    // Since g_is64 lives on device, pass both candidates.
    {
        // dst base for int32 layout:
        const int* dst32 = adj + Ee;
        // dst base for int64 layout (in int32 words):
        const int* dst64 = adj + 2 * (size_t)Ee;
        // Use a tiny trampoline: count/scatter pick base via g_is64.
        // We encode: pass adj (src base) and both dst bases via separate launches is messy;
        // instead kernels receive both pointers.
        init_deg_kernel<<<(Nn + T - 1) / T, T>>>(Nn);
        // count over dst
        // (kernel selects base pointer internally)
        struct {} _;
        (void)_;
        // fused into dedicated kernels below:
        extern __global__ void count2_kernel(const int*, const int*, int);
        extern __global__ void scatter2_kernel(const int*, const int*, const int*, int, int);
        count2_kernel<<<(Ee + T - 1) / T, T>>>(dst32, dst64, Ee);
        scan_kernel<<<1, 1024>>>(Nn);
        cursor_kernel<<<(Nn + T - 1) / T, T>>>(Nn);
        scatter2_kernel<<<(Ee + Nn + T - 1) / T, T>>>(adj, dst32, dst64, Ee, Nn);
    }

    // layer 1: K=512 -> DO=128
    dim3 g128((Nn + 127) / 128, 2);
    sgemm_kernel<false><<<g128, 256>>>(data, W1, Nn, 512, 128);
    alpha_kernel<128><<<warpGrid, T>>>(as1, ad1, Nn);
    aggregate_kernel<128, true><<<warpGrid, T>>>(b1, nullptr, Nn);

    // layer 2: K=128 -> DO=128
    sgemm_kernel<true><<<g128, 256>>>(nullptr, W2, Nn, 128, 128);
    alpha_kernel<128><<<warpGrid, T>>>(as2, ad2, Nn);
    aggregate_kernel<128, true><<<warpGrid, T>>>(b2, nullptr, Nn);

    // layer 3: K=128 -> DO=64
    dim3 g64((Nn + 127) / 128, 1);
    sgemm_kernel<true><<<g64, 256>>>(nullptr, W3, Nn, 128, 64);
    alpha_kernel<64><<<warpGrid, T>>>(as3, ad3, Nn);
    aggregate_kernel<64, false><<<warpGrid, T>>>(b3, (float*)d_out, Nn);
}

// dtype-flexible count/scatter (defined after launch for the extern decls above)
__global__ void count2_kernel(const int* __restrict__ dst32,
                              const int* __restrict__ dst64, int e) {
    int i = blockIdx.x * blockDim.x + threadIdx.x;
    if (i >= e) return;
    int is64 = g_is64;
    int d = is64 ? dst64[2 * i] : dst32[i];
    atomicAdd(&g_deg[d], 1);
}

__global__ void scatter2_kernel(const int* __restrict__ src,
                                const int* __restrict__ dst32,
                                const int* __restrict__ dst64, int e, int n) {
    int i = blockIdx.x * blockDim.x + threadIdx.x;
    int is64 = g_is64;
    if (i < e) {
        int d = is64 ? dst64[2 * i] : dst32[i];
        int s = is64 ? src[2 * i] : src[i];
        int p = atomicAdd(&g_cur[d], 1);
        g_srcs[p] = s;
    } else if (i < e + n) {
        int v = i - e;                      // self-loop
        int p = atomicAdd(&g_cur[v], 1);
        g_srcs[p] = v;
    }
}

// round 4
// speedup vs baseline: 1.5202x; 1.5202x over previous
#include <cuda_runtime.h>
#include <cuda_bf16.h>
#include <cstdint>

#define MAXN 100000
#define MAXE 1600000
#define MAXT (MAXE + MAXN)

// ---------------- scratch (static device globals; no runtime allocation) ----------------
__device__ __align__(16) float g_h[(size_t)MAXN * 128];   // per-layer h = x @ W
__device__ __align__(16) float g_x[(size_t)MAXN * 128];   // activations between layers
__device__ float g_as[MAXN];
__device__ float g_ad[MAXN];
__device__ int   g_deg[MAXN];
__device__ int   g_off[MAXN + 1];
__device__ int   g_cur[MAXN];
__device__ int   g_srcs[MAXT];
__device__ int   g_is64;
__device__ int   g_bsum[512];
__device__ __align__(8) __nv_bfloat16 g_Bhi[128 * 512];   // W^T hi  [N, K]
__device__ __align__(8) __nv_bfloat16 g_Blo[128 * 512];   // W^T lo  [N, K]

// ================= helpers =================
__device__ __forceinline__ uint32_t smem_u32(const void* p) {
    uint32_t a;
    asm("{ .reg .u64 t; cvta.to.shared.u64 t, %1; cvt.u32.u64 %0, t; }" : "=r"(a) : "l"(p));
    return a;
}
__device__ __forceinline__ uint32_t pack_bf16(float a, float b) {  // a -> low, b -> high
    uint32_t r;
    asm("cvt.rn.bf16x2.f32 %0, %1, %2;" : "=r"(r) : "f"(b), "f"(a));
    return r;
}
__device__ __forceinline__ float bf16_round(float x) {
    return __bfloat162float(__float2bfloat16(x));
}
__device__ __forceinline__ void ldm_x4(uint32_t* r, uint32_t addr) {
    asm volatile("ldmatrix.sync.aligned.m8n8.x4.shared.b16 {%0,%1,%2,%3}, [%4];"
                 : "=r"(r[0]), "=r"(r[1]), "=r"(r[2]), "=r"(r[3]) : "r"(addr));
}
__device__ __forceinline__ void ldm_x2(uint32_t* r, uint32_t addr) {
    asm volatile("ldmatrix.sync.aligned.m8n8.x2.shared.b16 {%0,%1}, [%2];"
                 : "=r"(r[0]), "=r"(r[1]) : "r"(addr));
}
__device__ __forceinline__ void mma_bf16(float* c, const uint32_t* a, const uint32_t* b) {
    asm volatile(
        "mma.sync.aligned.m16n8k16.row.col.f32.bf16.bf16.f32 "
        "{%0,%1,%2,%3},{%4,%5,%6,%7},{%8,%9},{%0,%1,%2,%3};"
        : "+f"(c[0]), "+f"(c[1]), "+f"(c[2]), "+f"(c[3])
        : "r"(a[0]), "r"(a[1]), "r"(a[2]), "r"(a[3]), "r"(b[0]), "r"(b[1]));
}

// ---------------- adjacency dtype detection ----------------
__global__ void detect_kernel(const int* __restrict__ w) {
    if (threadIdx.x == 0) {
        int all0 = 1;
        #pragma unroll 1
        for (int i = 0; i < 64; i++)
            if (w[2 * i + 1] != 0) { all0 = 0; break; }
        g_is64 = all0;
    }
}

// ---------------- CSR build ----------------
__global__ void init_deg_kernel(int n) {
    int i = blockIdx.x * blockDim.x + threadIdx.x;
    if (i < n) g_deg[i] = 1;  // self-loop
}

__global__ void count2_kernel(const int* __restrict__ dst32,
                              const int* __restrict__ dst64, int e) {
    int i = blockIdx.x * blockDim.x + threadIdx.x;
    if (i >= e) return;
    int is64 = g_is64;
    int d = is64 ? dst64[2 * i] : dst32[i];
    atomicAdd(&g_deg[d], 1);
}

#define SCAN_BS 512
__global__ void blockscan_kernel(int n) {
    __shared__ int sh[SCAN_BS];
    int t = threadIdx.x;
    int i = blockIdx.x * SCAN_BS + t;
    int v = (i < n) ? g_deg[i] : 0;
    sh[t] = v;
    __syncthreads();
    #pragma unroll
    for (int d = 1; d < SCAN_BS; d <<= 1) {
        int x = (t >= d) ? sh[t - d] : 0;
        __syncthreads();
        sh[t] += x;
        __syncthreads();
    }
    if (i < n) g_off[i] = sh[t] - v;
    if (t == SCAN_BS - 1) g_bsum[blockIdx.x] = sh[t];
}

__global__ void bsumscan_kernel(int nb, int n) {
    __shared__ int sh[512];
    int t = threadIdx.x;
    int v = (t < nb) ? g_bsum[t] : 0;
    sh[t] = v;
    __syncthreads();
    #pragma unroll
    for (int d = 1; d < 512; d <<= 1) {
        int x = (t >= d) ? sh[t - d] : 0;
        __syncthreads();
        sh[t] += x;
        __syncthreads();
    }
    if (t < nb) g_bsum[t] = sh[t] - v;
    if (t == 511) g_off[n] = sh[511];
}

__global__ void addoff_kernel(int n) {
    int i = blockIdx.x * blockDim.x + threadIdx.x;
    if (i < n) {
        int o = g_off[i] + g_bsum[i >> 9];
        g_off[i] = o;
        g_cur[i] = o;
    }
}

__global__ void scatter2_kernel(const int* __restrict__ src,
                                const int* __restrict__ dst32,
                                const int* __restrict__ dst64, int e, int n) {
    int i = blockIdx.x * blockDim.x + threadIdx.x;
    int is64 = g_is64;
    if (i < e) {
        int d = is64 ? dst64[2 * i] : dst32[i];
        int s = is64 ? src[2 * i] : src[i];
        int p = atomicAdd(&g_cur[d], 1);
        g_srcs[p] = s;
    } else if (i < e + n) {
        int v = i - e;
        int p = atomicAdd(&g_cur[v], 1);
        g_srcs[p] = v;
    }
}

// ---------------- W transpose + bf16 hi/lo split ----------------
__global__ void wsplit_kernel(const float* __restrict__ W, int K, int Nd) {
    int i = blockIdx.x * blockDim.x + threadIdx.x;
    if (i >= K * Nd) return;
    int k = i / Nd, nn = i % Nd;
    float x = W[i];
    float h = bf16_round(x);
    g_Bhi[(size_t)nn * K + k] = __float2bfloat16(h);
    g_Blo[(size_t)nn * K + k] = __float2bfloat16(x - h);
}

// ---------------- mma.sync bf16-split GEMM: g_h[M,NDIM] = A[M,K] @ W[K,NDIM] ----------------
// Block: 256 thr (8 warps), tile 128 x NDIM, K-chunk = 64.
// smem: Ahi[128][64] Alo[128][64] (bf16, 128B swizzled rows), Bhi/Blo[NDIM][64].
template <int NDIM>
__global__ void __launch_bounds__(256, 2)
mma_gemm_kernel(const float* __restrict__ Ain, int useGX, int M, int K) {
    constexpr int ABYTES = 128 * 128;           // 16KB per A tile
    constexpr int BBYTES = NDIM * 128;
    constexpr int NT = NDIM / 8;
    extern __shared__ char smraw[];
    char* smem = (char*)(((uintptr_t)smraw + 1023) & ~(uintptr_t)1023);
    uint32_t aHiB = smem_u32(smem);
    uint32_t aLoB = aHiB + ABYTES;
    uint32_t bHiB = aHiB + 2 * ABYTES;
    uint32_t bLoB = bHiB + BBYTES;

    const float* A = useGX ? g_x : Ain;
    const int tid = threadIdx.x, wid = tid >> 5, lane = tid & 31;
    const int rowBase = blockIdx.x * 128;

    float acc[NT][4];
    #pragma unroll
    for (int nt = 0; nt < NT; nt++)
        #pragma unroll
        for (int q = 0; q < 4; q++) acc[nt][q] = 0.f;

    // per-lane ldmatrix address components
    const int Rw = wid * 16;
    const int aRow = Rw + (lane & 7) + ((lane >> 3) & 1) * 8;
    const uint32_t aRowOff = (uint32_t)aRow * 128;
    const uint32_t aSwz = (uint32_t)(aRow & 7) << 4;
    const uint32_t aHalf = ((lane >> 4) & 1) * 16;
    const uint32_t bRow = (lane & 7);
    const uint32_t bRowOff = bRow * 128;
    const uint32_t bSwz = bRow << 4;
    const uint32_t bHalf = ((lane >> 3) & 1) * 16;

    // staging indices
    const int sr = tid >> 4;            // 0..15
    const int cg = (tid & 15) * 4;      // bf16 col group
    const uint32_t stCol = (uint32_t)(cg * 2);

    const int nChunks = K >> 6;
    for (int c = 0; c < nChunks; c++) {
        const int k0 = c << 6;
        // ---- stage A (128 rows x 64 cols) ----
        #pragma unroll
        for (int p = 0; p < 8; p++) {
            int r = p * 16 + sr;
            int gr = rowBase + r;
            float4 v = make_float4(0.f, 0.f, 0.f, 0.f);
            if (gr < M)
                v = *reinterpret_cast<const float4*>(&A[(size_t)gr * K + k0 + cg]);
            float h0 = bf16_round(v.x), h1 = bf16_round(v.y);
            float h2 = bf16_round(v.z), h3 = bf16_round(v.w);
            uint32_t off = (uint32_t)r * 128 + (stCol ^ ((uint32_t)(r & 7) << 4));
            *(uint32_t*)(smem + (off))              = pack_bf16(v.x, v.y);
            *(uint32_t*)(smem + (off + 4))          = pack_bf16(v.z, v.w);
            *(uint32_t*)(smem + ABYTES + off)       = pack_bf16(v.x - h0, v.y - h1);
            *(uint32_t*)(smem + ABYTES + off + 4)   = pack_bf16(v.z - h2, v.w - h3);
        }
        // ---- stage B (NDIM rows x 64 cols, pre-split bf16) ----
        #pragma unroll
        for (int p = 0; p < NDIM / 16; p++) {
            int r = p * 16 + sr;
            uint2 vh = *reinterpret_cast<const uint2*>(&g_Bhi[(size_t)r * K + k0 + cg]);
            uint2 vl = *reinterpret_cast<const uint2*>(&g_Blo[(size_t)r * K + k0 + cg]);
            uint32_t off = (uint32_t)r * 128 + (stCol ^ ((uint32_t)(r & 7) << 4));
            *(uint32_t*)(smem + 2 * ABYTES + off)              = vh.x;
            *(uint32_t*)(smem + 2 * ABYTES + off + 4)          = vh.y;
            *(uint32_t*)(smem + 2 * ABYTES + BBYTES + off)     = vl.x;
            *(uint32_t*)(smem + 2 * ABYTES + BBYTES + off + 4) = vl.y;
        }
        __syncthreads();

        // ---- compute ----
        #pragma unroll
        for (int kt = 0; kt < 4; kt++) {
            uint32_t aoff = aRowOff + (((uint32_t)kt * 32 + aHalf) ^ aSwz);
            uint32_t ahi[4], alo[4];
            ldm_x4(ahi, aHiB + aoff);
            ldm_x4(alo, aLoB + aoff);
            uint32_t bcol = ((uint32_t)kt * 32 + bHalf) ^ bSwz;
            #pragma unroll
            for (int nt = 0; nt < NT; nt++) {
                uint32_t boff = (uint32_t)nt * 1024 + bRowOff + bcol;
                uint32_t bhi[2], blo[2];
                ldm_x2(bhi, bHiB + boff);
                ldm_x2(blo, bLoB + boff);
                mma_bf16(acc[nt], ahi, bhi);
                mma_bf16(acc[nt], ahi, blo);
                mma_bf16(acc[nt], alo, bhi);
            }
        }
        __syncthreads();
    }

    // ---- epilogue ----
    int r0 = rowBase + Rw + (lane >> 2);
    int colb = (lane & 3) * 2;
    #pragma unroll
    for (int nt = 0; nt < NT; nt++) {
        if (r0 < M)
            *reinterpret_cast<float2*>(&g_h[(size_t)r0 * NDIM + nt * 8 + colb]) =
                make_float2(acc[nt][0], acc[nt][1]);
        if (r0 + 8 < M)
            *reinterpret_cast<float2*>(&g_h[(size_t)(r0 + 8) * NDIM + nt * 8 + colb]) =
                make_float2(acc[nt][2], acc[nt][3]);
    }
}

// ---------------- per-node attention dots ----------------
template <int DO>
__global__ void alpha_kernel(const float* __restrict__ a_src,
                             const float* __restrict__ a_dst, int n) {
    constexpr int VEC = DO / 32;
    int w = (blockIdx.x * blockDim.x + threadIdx.x) >> 5;
    int lane = threadIdx.x & 31;
    if (w >= n) return;
    float s = 0.f, d = 0.f;
    const float* hp = &g_h[(size_t)w * DO + lane * VEC];
    #pragma unroll
    for (int k = 0; k < VEC; k++) {
        float hv = hp[k];
        s = fmaf(hv, a_src[lane * VEC + k], s);
        d = fmaf(hv, a_dst[lane * VEC + k], d);
    }
    #pragma unroll
    for (int o = 16; o; o >>= 1) {
        s += __shfl_xor_sync(0xffffffffu, s, o);
        d += __shfl_xor_sync(0xffffffffu, d, o);
    }
    if (lane == 0) { g_as[w] = s; g_ad[w] = d; }
}

// ---------------- segment softmax + aggregation (warp per dst) ----------------
template <int DO, bool TO_GX>
__global__ void aggregate_kernel(const float* __restrict__ bias,
                                 float* __restrict__ outp, int n) {
    constexpr int VEC = DO / 32;
    int node = (blockIdx.x * blockDim.x + threadIdx.x) >> 5;
    int lane = threadIdx.x & 31;
    if (node >= n) return;
    int s0 = g_off[node], s1 = g_off[node + 1];
    float adn = g_ad[node];

    float m = -1e30f;
    for (int j = s0 + lane; j < s1; j += 32) {
        float v = g_as[g_srcs[j]] + adn;
        v = v > 0.f ? v : 0.2f * v;
        m = fmaxf(m, v);
    }
    #pragma unroll
    for (int o = 16; o; o >>= 1) m = fmaxf(m, __shfl_xor_sync(0xffffffffu, m, o));

    float acc[VEC];
    #pragma unroll
    for (int k = 0; k < VEC; k++) acc[k] = 0.f;
    float ssum = 0.f;
    for (int j = s0; j < s1; ++j) {
        int s = g_srcs[j];
        float v = g_as[s] + adn;
        v = v > 0.f ? v : 0.2f * v;
        float w = __expf(v - m);
        ssum += w;
        const float* hp = &g_h[(size_t)s * DO + lane * VEC];
        if constexpr (VEC == 4) {
            float4 hv = *reinterpret_cast<const float4*>(hp);
            acc[0] = fmaf(w, hv.x, acc[0]);
            acc[1] = fmaf(w, hv.y, acc[1]);
            acc[2] = fmaf(w, hv.z, acc[2]);
            acc[3] = fmaf(w, hv.w, acc[3]);
        } else {
            float2 hv = *reinterpret_cast<const float2*>(hp);
            acc[0] = fmaf(w, hv.x, acc[0]);
            acc[1] = fmaf(w, hv.y, acc[1]);
        }
    }
    float inv = 1.f / ssum;
    #pragma unroll
    for (int k = 0; k < VEC; k++) {
        float o = fmaf(acc[k], inv, bias[lane * VEC + k]);
        acc[k] = o > 0.f ? o : 0.25f * o;
    }
    float* op = TO_GX ? &g_x[(size_t)node * DO + lane * VEC]
                      : &outp[(size_t)node * DO + lane * VEC];
    if constexpr (VEC == 4)
        *reinterpret_cast<float4*>(op) = make_float4(acc[0], acc[1], acc[2], acc[3]);
    else
        *reinterpret_cast<float2*>(op) = make_float2(acc[0], acc[1]);
}

// ---------------- launch ----------------
extern "C" void kernel_launch(void* const* d_in, const int* in_sizes, int n_in,
                              void* d_out, int out_size) {
    const float* data = (const float*)d_in[0];
    const int*   adj  = (const int*)d_in[1];
    const float* W1  = (const float*)d_in[2];
    const float* as1 = (const float*)d_in[3];
    const float* ad1 = (const float*)d_in[4];
    const float* b1  = (const float*)d_in[5];
    const float* W2  = (const float*)d_in[6];
    const float* as2 = (const float*)d_in[7];
    const float* ad2 = (const float*)d_in[8];
    const float* b2  = (const float*)d_in[9];
    const float* W3  = (const float*)d_in[10];
    const float* as3 = (const float*)d_in[11];
    const float* ad3 = (const float*)d_in[12];
    const float* b3  = (const float*)d_in[13];

    int Nn = in_sizes[0] / 512;
    int Ee = in_sizes[1] / 2;

    const int SM128 = 2 * 128 * 128 + 2 * 128 * 128 + 1024;  // 64KB + pad
    const int SM64  = 2 * 128 * 128 + 2 * 64 * 128 + 1024;   // 48KB + pad
    cudaFuncSetAttribute(mma_gemm_kernel<128>,
                         cudaFuncAttributeMaxDynamicSharedMemorySize, SM128);
    cudaFuncSetAttribute(mma_gemm_kernel<64>,
                         cudaFuncAttributeMaxDynamicSharedMemorySize, SM64);

    const int T = 256;
    int warpGrid = (Nn * 32 + T - 1) / T;
    const int* dst32 = adj + Ee;
    const int* dst64 = adj + 2 * (size_t)Ee;

    // CSR build (shared across layers)
    detect_kernel<<<1, 32>>>(adj);
    init_deg_kernel<<<(Nn + T - 1) / T, T>>>(Nn);
    count2_kernel<<<(Ee + T - 1) / T, T>>>(dst32, dst64, Ee);
    int nb = (Nn + SCAN_BS - 1) / SCAN_BS;
    blockscan_kernel<<<nb, SCAN_BS>>>(Nn);
    bsumscan_kernel<<<1, 512>>>(nb, Nn);
    addoff_kernel<<<(Nn + T - 1) / T, T>>>(Nn);
    scatter2_kernel<<<(Ee + Nn + T - 1) / T, T>>>(adj, dst32, dst64, Ee, Nn);

    int gBlocks = (Nn + 127) / 128;

    // layer 1: K=512 -> 128
    wsplit_kernel<<<(512 * 128 + T - 1) / T, T>>>(W1, 512, 128);
    mma_gemm_kernel<128><<<gBlocks, 256, SM128>>>(data, 0, Nn, 512);
    alpha_kernel<128><<<warpGrid, T>>>(as1, ad1, Nn);
    aggregate_kernel<128, true><<<warpGrid, T>>>(b1, nullptr, Nn);

    // layer 2: K=128 -> 128
    wsplit_kernel<<<(128 * 128 + T - 1) / T, T>>>(W2, 128, 128);
    mma_gemm_kernel<128><<<gBlocks, 256, SM128>>>(nullptr, 1, Nn, 128);
    alpha_kernel<128><<<warpGrid, T>>>(as2, ad2, Nn);
    aggregate_kernel<128, true><<<warpGrid, T>>>(b2, nullptr, Nn);

    // layer 3: K=128 -> 64
    wsplit_kernel<<<(128 * 64 + T - 1) / T, T>>>(W3, 128, 64);
    mma_gemm_kernel<64><<<gBlocks, 256, SM64>>>(nullptr, 1, Nn, 128);
    alpha_kernel<64><<<warpGrid, T>>>(as3, ad3, Nn);
    aggregate_kernel<64, false><<<warpGrid, T>>>(b3, (float*)d_out, Nn);
}

// round 5
// speedup vs baseline: 1.6719x; 1.0998x over previous
#include <cuda_runtime.h>
#include <cuda_bf16.h>
#include <cstdint>

#define MAXN 100000
#define MAXE 1600000
#define MAXT (MAXE + MAXN)

// ---------------- scratch (static device globals; no runtime allocation) ----------------
__device__ __align__(16) float g_h[(size_t)MAXN * 128];   // per-layer h = x @ W
__device__ __align__(16) float g_x[(size_t)MAXN * 128];   // activations between layers
__device__ float g_as[MAXN];
__device__ float g_ad[MAXN];
__device__ int   g_deg[MAXN];
__device__ int   g_off[MAXN + 1];
__device__ int   g_cur[MAXN];
__device__ int   g_srcs[MAXT];
__device__ int   g_is64;
__device__ int   g_bsum[512];
__device__ __align__(8) __nv_bfloat16 g_Bhi[128 * 512];   // W^T hi  [N, K]
__device__ __align__(8) __nv_bfloat16 g_Blo[128 * 512];   // W^T lo  [N, K]

// ================= helpers =================
__device__ __forceinline__ uint32_t smem_u32(const void* p) {
    uint32_t a;
    asm("{ .reg .u64 t; cvta.to.shared.u64 t, %1; cvt.u32.u64 %0, t; }" : "=r"(a) : "l"(p));
    return a;
}
__device__ __forceinline__ uint32_t pack_bf16(float a, float b) {  // a -> low, b -> high
    uint32_t r;
    asm("cvt.rn.bf16x2.f32 %0, %1, %2;" : "=r"(r) : "f"(b), "f"(a));
    return r;
}
__device__ __forceinline__ float bf16_round(float x) {
    return __bfloat162float(__float2bfloat16(x));
}
__device__ __forceinline__ void ldm_x4(uint32_t* r, uint32_t addr) {
    asm volatile("ldmatrix.sync.aligned.m8n8.x4.shared.b16 {%0,%1,%2,%3}, [%4];"
                 : "=r"(r[0]), "=r"(r[1]), "=r"(r[2]), "=r"(r[3]) : "r"(addr));
}
__device__ __forceinline__ void ldm_x2(uint32_t* r, uint32_t addr) {
    asm volatile("ldmatrix.sync.aligned.m8n8.x2.shared.b16 {%0,%1}, [%2];"
                 : "=r"(r[0]), "=r"(r[1]) : "r"(addr));
}
__device__ __forceinline__ void mma_bf16(float* c, const uint32_t* a, const uint32_t* b) {
    asm volatile(
        "mma.sync.aligned.m16n8k16.row.col.f32.bf16.bf16.f32 "
        "{%0,%1,%2,%3},{%4,%5,%6,%7},{%8,%9},{%0,%1,%2,%3};"
        : "+f"(c[0]), "+f"(c[1]), "+f"(c[2]), "+f"(c[3])
        : "r"(a[0]), "r"(a[1]), "r"(a[2]), "r"(a[3]), "r"(b[0]), "r"(b[1]));
}

// ---------------- adjacency dtype detection ----------------
__global__ void detect_kernel(const int* __restrict__ w) {
    if (threadIdx.x == 0) {
        int all0 = 1;
        #pragma unroll 1
        for (int i = 0; i < 64; i++)
            if (w[2 * i + 1] != 0) { all0 = 0; break; }
        g_is64 = all0;
    }
}

// ---------------- CSR build ----------------
__global__ void init_deg_kernel(int n) {
    int i = blockIdx.x * blockDim.x + threadIdx.x;
    if (i < n) g_deg[i] = 1;  // self-loop
}

__global__ void count2_kernel(const int* __restrict__ dst32,
                              const int* __restrict__ dst64, int e) {
    int i = blockIdx.x * blockDim.x + threadIdx.x;
    if (i >= e) return;
    int is64 = g_is64;
    int d = is64 ? dst64[2 * i] : dst32[i];
    atomicAdd(&g_deg[d], 1);
}

#define SCAN_BS 512
__global__ void blockscan_kernel(int n) {
    __shared__ int sh[SCAN_BS];
    int t = threadIdx.x;
    int i = blockIdx.x * SCAN_BS + t;
    int v = (i < n) ? g_deg[i] : 0;
    sh[t] = v;
    __syncthreads();
    #pragma unroll
    for (int d = 1; d < SCAN_BS; d <<= 1) {
        int x = (t >= d) ? sh[t - d] : 0;
        __syncthreads();
        sh[t] += x;
        __syncthreads();
    }
    if (i < n) g_off[i] = sh[t] - v;
    if (t == SCAN_BS - 1) g_bsum[blockIdx.x] = sh[t];
}

__global__ void bsumscan_kernel(int nb, int n) {
    __shared__ int sh[512];
    int t = threadIdx.x;
    int v = (t < nb) ? g_bsum[t] : 0;
    sh[t] = v;
    __syncthreads();
    #pragma unroll
    for (int d = 1; d < 512; d <<= 1) {
        int x = (t >= d) ? sh[t - d] : 0;
        __syncthreads();
        sh[t] += x;
        __syncthreads();
    }
    if (t < nb) g_bsum[t] = sh[t] - v;
    if (t == 511) g_off[n] = sh[511];
}

__global__ void addoff_kernel(int n) {
    int i = blockIdx.x * blockDim.x + threadIdx.x;
    if (i < n) {
        int o = g_off[i] + g_bsum[i >> 9];
        g_off[i] = o;
        g_cur[i] = o;
    }
}

__global__ void scatter2_kernel(const int* __restrict__ src,
                                const int* __restrict__ dst32,
                                const int* __restrict__ dst64, int e, int n) {
    int i = blockIdx.x * blockDim.x + threadIdx.x;
    int is64 = g_is64;
    if (i < e) {
        int d = is64 ? dst64[2 * i] : dst32[i];
        int s = is64 ? src[2 * i] : src[i];
        int p = atomicAdd(&g_cur[d], 1);
        g_srcs[p] = s;
    } else if (i < e + n) {
        int v = i - e;
        int p = atomicAdd(&g_cur[v], 1);
        g_srcs[p] = v;
    }
}

// ---------------- W transpose + bf16 hi/lo split ----------------
__global__ void wsplit_kernel(const float* __restrict__ W, int K, int Nd) {
    int i = blockIdx.x * blockDim.x + threadIdx.x;
    if (i >= K * Nd) return;
    int k = i / Nd, nn = i % Nd;
    float x = W[i];
    float h = bf16_round(x);
    g_Bhi[(size_t)nn * K + k] = __float2bfloat16(h);
    g_Blo[(size_t)nn * K + k] = __float2bfloat16(x - h);
}

// ---------------- mma.sync bf16-split GEMM + fused alpha dots ----------------
// Block: 256 thr (8 warps), tile 128 x NDIM, K-chunk = 64.
// Register double-buffered A staging; epilogue computes g_as/g_ad.
template <int NDIM>
__global__ void __launch_bounds__(256, 2)
mma_gemm_kernel(const float* __restrict__ Ain, int useGX, int M, int K,
                const float* __restrict__ a_src, const float* __restrict__ a_dst) {
    constexpr int ABYTES = 128 * 128;           // 16KB per A tile
    constexpr int BBYTES = NDIM * 128;
    constexpr int NT = NDIM / 8;
    extern __shared__ char smraw[];
    char* smem = (char*)(((uintptr_t)smraw + 1023) & ~(uintptr_t)1023);
    uint32_t aHiB = smem_u32(smem);
    uint32_t aLoB = aHiB + ABYTES;
    uint32_t bHiB = aHiB + 2 * ABYTES;
    uint32_t bLoB = bHiB + BBYTES;

    const float* A = useGX ? g_x : Ain;
    const int tid = threadIdx.x, wid = tid >> 5, lane = tid & 31;
    const int rowBase = blockIdx.x * 128;

    float acc[NT][4];
    #pragma unroll
    for (int nt = 0; nt < NT; nt++)
        #pragma unroll
        for (int q = 0; q < 4; q++) acc[nt][q] = 0.f;

    // per-lane ldmatrix address components
    const int Rw = wid * 16;
    const int aRow = Rw + (lane & 7) + ((lane >> 3) & 1) * 8;
    const uint32_t aRowOff = (uint32_t)aRow * 128;
    const uint32_t aSwz = (uint32_t)(aRow & 7) << 4;
    const uint32_t aHalf = ((lane >> 4) & 1) * 16;
    const uint32_t bRow = (lane & 7);
    const uint32_t bRowOff = bRow * 128;
    const uint32_t bSwz = bRow << 4;
    const uint32_t bHalf = ((lane >> 3) & 1) * 16;

    // staging indices
    const int sr = tid >> 4;            // 0..15
    const int cg = (tid & 15) * 4;      // col group (4 floats)
    const uint32_t stCol = (uint32_t)(cg * 2);

    const int nChunks = K >> 6;

    // ---- register prefetch of A chunk 0 ----
    float4 pref[8];
    {
        #pragma unroll
        for (int p = 0; p < 8; p++) {
            int gr = rowBase + p * 16 + sr;
            pref[p] = make_float4(0.f, 0.f, 0.f, 0.f);
            if (gr < M)
                pref[p] = *reinterpret_cast<const float4*>(&A[(size_t)gr * K + cg]);
        }
    }

    for (int c = 0; c < nChunks; c++) {
        // ---- store staged A (from registers) ----
        #pragma unroll
        for (int p = 0; p < 8; p++) {
            int r = p * 16 + sr;
            float4 v = pref[p];
            float h0 = bf16_round(v.x), h1 = bf16_round(v.y);
            float h2 = bf16_round(v.z), h3 = bf16_round(v.w);
            uint32_t off = (uint32_t)r * 128 + (stCol ^ ((uint32_t)(r & 7) << 4));
            *(uint32_t*)(smem + (off))            = pack_bf16(v.x, v.y);
            *(uint32_t*)(smem + (off + 4))        = pack_bf16(v.z, v.w);
            *(uint32_t*)(smem + ABYTES + off)     = pack_bf16(v.x - h0, v.y - h1);
            *(uint32_t*)(smem + ABYTES + off + 4) = pack_bf16(v.z - h2, v.w - h3);
        }
        // ---- stage B (NDIM rows x 64 cols, pre-split bf16, L2-resident) ----
        {
            const int k0 = c << 6;
            #pragma unroll
            for (int p = 0; p < NDIM / 16; p++) {
                int r = p * 16 + sr;
                uint2 vh = *reinterpret_cast<const uint2*>(&g_Bhi[(size_t)r * K + k0 + cg]);
                uint2 vl = *reinterpret_cast<const uint2*>(&g_Blo[(size_t)r * K + k0 + cg]);
                uint32_t off = (uint32_t)r * 128 + (stCol ^ ((uint32_t)(r & 7) << 4));
                *(uint32_t*)(smem + 2 * ABYTES + off)              = vh.x;
                *(uint32_t*)(smem + 2 * ABYTES + off + 4)          = vh.y;
                *(uint32_t*)(smem + 2 * ABYTES + BBYTES + off)     = vl.x;
                *(uint32_t*)(smem + 2 * ABYTES + BBYTES + off + 4) = vl.y;
            }
        }
        __syncthreads();

        // ---- prefetch A chunk c+1 (overlaps with MMA below) ----
        if (c + 1 < nChunks) {
            const int k1 = (c + 1) << 6;
            #pragma unroll
            for (int p = 0; p < 8; p++) {
                int gr = rowBase + p * 16 + sr;
                float4 z = make_float4(0.f, 0.f, 0.f, 0.f);
                pref[p] = z;
                if (gr < M)
                    pref[p] = *reinterpret_cast<const float4*>(&A[(size_t)gr * K + k1 + cg]);
            }
        }

        // ---- compute ----
        #pragma unroll
        for (int kt = 0; kt < 4; kt++) {
            uint32_t aoff = aRowOff + (((uint32_t)kt * 32 + aHalf) ^ aSwz);
            uint32_t ahi[4], alo[4];
            ldm_x4(ahi, aHiB + aoff);
            ldm_x4(alo, aLoB + aoff);
            uint32_t bcol = ((uint32_t)kt * 32 + bHalf) ^ bSwz;
            #pragma unroll
            for (int nt = 0; nt < NT; nt++) {
                uint32_t boff = (uint32_t)nt * 1024 + bRowOff + bcol;
                uint32_t bhi[2], blo[2];
                ldm_x2(bhi, bHiB + boff);
                ldm_x2(blo, bLoB + boff);
                mma_bf16(acc[nt], ahi, bhi);
                mma_bf16(acc[nt], ahi, blo);
                mma_bf16(acc[nt], alo, bhi);
            }
        }
        __syncthreads();
    }

    // ---- epilogue: write h + fused alpha dots ----
    int r0 = rowBase + Rw + (lane >> 2);
    int colb = (lane & 3) * 2;
    float s1p = 0.f, d1p = 0.f, s2p = 0.f, d2p = 0.f;
    #pragma unroll
    for (int nt = 0; nt < NT; nt++) {
        int col = nt * 8 + colb;
        float a0 = a_src[col], a1 = a_src[col + 1];
        float e0 = a_dst[col], e1 = a_dst[col + 1];
        s1p = fmaf(acc[nt][0], a0, fmaf(acc[nt][1], a1, s1p));
        d1p = fmaf(acc[nt][0], e0, fmaf(acc[nt][1], e1, d1p));
        s2p = fmaf(acc[nt][2], a0, fmaf(acc[nt][3], a1, s2p));
        d2p = fmaf(acc[nt][2], e0, fmaf(acc[nt][3], e1, d2p));
        if (r0 < M)
            *reinterpret_cast<float2*>(&g_h[(size_t)r0 * NDIM + col]) =
                make_float2(acc[nt][0], acc[nt][1]);
        if (r0 + 8 < M)
            *reinterpret_cast<float2*>(&g_h[(size_t)(r0 + 8) * NDIM + col]) =
                make_float2(acc[nt][2], acc[nt][3]);
    }
    #pragma unroll
    for (int o = 1; o <= 2; o <<= 1) {
        s1p += __shfl_xor_sync(0xffffffffu, s1p, o);
        d1p += __shfl_xor_sync(0xffffffffu, d1p, o);
        s2p += __shfl_xor_sync(0xffffffffu, s2p, o);
        d2p += __shfl_xor_sync(0xffffffffu, d2p, o);
    }
    if ((lane & 3) == 0) {
        if (r0 < M)     { g_as[r0] = s1p;     g_ad[r0] = d1p; }
        if (r0 + 8 < M) { g_as[r0 + 8] = s2p; g_ad[r0 + 8] = d2p; }
    }
}

// ---------------- segment softmax + aggregation (warp per dst) ----------------
template <int DO, bool TO_GX>
__global__ void aggregate_kernel(const float* __restrict__ bias,
                                 float* __restrict__ outp, int n) {
    constexpr int VEC = DO / 32;
    int node = (blockIdx.x * blockDim.x + threadIdx.x) >> 5;
    int lane = threadIdx.x & 31;
    if (node >= n) return;
    int s0 = g_off[node], s1 = g_off[node + 1];
    float adn = g_ad[node];

    float m = -1e30f;
    for (int j = s0 + lane; j < s1; j += 32) {
        float v = g_as[g_srcs[j]] + adn;
        v = v > 0.f ? v : 0.2f * v;
        m = fmaxf(m, v);
    }
    #pragma unroll
    for (int o = 16; o; o >>= 1) m = fmaxf(m, __shfl_xor_sync(0xffffffffu, m, o));

    float acc[VEC];
    #pragma unroll
    for (int k = 0; k < VEC; k++) acc[k] = 0.f;
    float ssum = 0.f;
    #pragma unroll 2
    for (int j = s0; j < s1; ++j) {
        int s = g_srcs[j];
        float v = g_as[s] + adn;
        v = v > 0.f ? v : 0.2f * v;
        float w = __expf(v - m);
        ssum += w;
        const float* hp = &g_h[(size_t)s * DO + lane * VEC];
        if constexpr (VEC == 4) {
            float4 hv = *reinterpret_cast<const float4*>(hp);
            acc[0] = fmaf(w, hv.x, acc[0]);
            acc[1] = fmaf(w, hv.y, acc[1]);
            acc[2] = fmaf(w, hv.z, acc[2]);
            acc[3] = fmaf(w, hv.w, acc[3]);
        } else {
            float2 hv = *reinterpret_cast<const float2*>(hp);
            acc[0] = fmaf(w, hv.x, acc[0]);
            acc[1] = fmaf(w, hv.y, acc[1]);
        }
    }
    float inv = 1.f / ssum;
    #pragma unroll
    for (int k = 0; k < VEC; k++) {
        float o = fmaf(acc[k], inv, bias[lane * VEC + k]);
        acc[k] = o > 0.f ? o : 0.25f * o;
    }
    float* op = TO_GX ? &g_x[(size_t)node * DO + lane * VEC]
                      : &outp[(size_t)node * DO + lane * VEC];
    if constexpr (VEC == 4)
        *reinterpret_cast<float4*>(op) = make_float4(acc[0], acc[1], acc[2], acc[3]);
    else
        *reinterpret_cast<float2*>(op) = make_float2(acc[0], acc[1]);
}

// ---------------- launch ----------------
extern "C" void kernel_launch(void* const* d_in, const int* in_sizes, int n_in,
                              void* d_out, int out_size) {
    const float* data = (const float*)d_in[0];
    const int*   adj  = (const int*)d_in[1];
    const float* W1  = (const float*)d_in[2];
    const float* as1 = (const float*)d_in[3];
    const float* ad1 = (const float*)d_in[4];
    const float* b1  = (const float*)d_in[5];
    const float* W2  = (const float*)d_in[6];
    const float* as2 = (const float*)d_in[7];
    const float* ad2 = (const float*)d_in[8];
    const float* b2  = (const float*)d_in[9];
    const float* W3  = (const float*)d_in[10];
    const float* as3 = (const float*)d_in[11];
    const float* ad3 = (const float*)d_in[12];
    const float* b3  = (const float*)d_in[13];

    int Nn = in_sizes[0] / 512;
    int Ee = in_sizes[1] / 2;

    const int SM128 = 2 * 128 * 128 + 2 * 128 * 128 + 1024;  // 64KB + pad
    const int SM64  = 2 * 128 * 128 + 2 * 64 * 128 + 1024;   // 48KB + pad
    cudaFuncSetAttribute(mma_gemm_kernel<128>,
                         cudaFuncAttributeMaxDynamicSharedMemorySize, SM128);
    cudaFuncSetAttribute(mma_gemm_kernel<64>,
                         cudaFuncAttributeMaxDynamicSharedMemorySize, SM64);

    const int T = 256;
    int warpGrid = (Nn * 32 + T - 1) / T;
    const int* dst32 = adj + Ee;
    const int* dst64 = adj + 2 * (size_t)Ee;

    // CSR build (shared across layers)
    detect_kernel<<<1, 32>>>(adj);
    init_deg_kernel<<<(Nn + T - 1) / T, T>>>(Nn);
    count2_kernel<<<(Ee + T - 1) / T, T>>>(dst32, dst64, Ee);
    int nb = (Nn + SCAN_BS - 1) / SCAN_BS;
    blockscan_kernel<<<nb, SCAN_BS>>>(Nn);
    bsumscan_kernel<<<1, 512>>>(nb, Nn);
    addoff_kernel<<<(Nn + T - 1) / T, T>>>(Nn);
    scatter2_kernel<<<(Ee + Nn + T - 1) / T, T>>>(adj, dst32, dst64, Ee, Nn);

    int gBlocks = (Nn + 127) / 128;

    // layer 1: K=512 -> 128
    wsplit_kernel<<<(512 * 128 + T - 1) / T, T>>>(W1, 512, 128);
    mma_gemm_kernel<128><<<gBlocks, 256, SM128>>>(data, 0, Nn, 512, as1, ad1);
    aggregate_kernel<128, true><<<warpGrid, T>>>(b1, nullptr, Nn);

    // layer 2: K=128 -> 128
    wsplit_kernel<<<(128 * 128 + T - 1) / T, T>>>(W2, 128, 128);
    mma_gemm_kernel<128><<<gBlocks, 256, SM128>>>(nullptr, 1, Nn, 128, as2, ad2);
    aggregate_kernel<128, true><<<warpGrid, T>>>(b2, nullptr, Nn);

    // layer 3: K=128 -> 64
    wsplit_kernel<<<(128 * 64 + T - 1) / T, T>>>(W3, 128, 64);
    mma_gemm_kernel<64><<<gBlocks, 256, SM64>>>(nullptr, 1, Nn, 128, as3, ad3);
    aggregate_kernel<64, false><<<warpGrid, T>>>(b3, (float*)d_out, Nn);
}

// round 6
// speedup vs baseline: 1.7934x; 1.0727x over previous
#include <cuda_runtime.h>
#include <cuda_bf16.h>
#include <cstdint>

#define MAXN 100000
#define MAXE 1600000
#define MAXT (MAXE + MAXN)

// ---------------- scratch (static device globals; no runtime allocation) ----------------
__device__ __align__(16) float g_h[(size_t)MAXN * 128];   // per-layer h = x @ W
__device__ __align__(16) float g_x[(size_t)MAXN * 128];   // activations between layers
__device__ float g_as[MAXN];
__device__ float g_ad[MAXN];
__device__ int   g_deg[MAXN];
__device__ int   g_off[MAXN + 1];
__device__ int   g_cur[MAXN];
__device__ int   g_srcs[MAXT];
__device__ int   g_is64;
__device__ int   g_bsum[512];
__device__ __align__(8) __nv_bfloat16 g_Bhi[128 * 512];   // W^T hi  [N, K]
__device__ __align__(8) __nv_bfloat16 g_Blo[128 * 512];   // W^T lo  [N, K]

// ================= helpers =================
__device__ __forceinline__ uint32_t smem_u32(const void* p) {
    uint32_t a;
    asm("{ .reg .u64 t; cvta.to.shared.u64 t, %1; cvt.u32.u64 %0, t; }" : "=r"(a) : "l"(p));
    return a;
}
__device__ __forceinline__ uint32_t pack_bf16(float a, float b) {  // a -> low, b -> high
    uint32_t r;
    asm("cvt.rn.bf16x2.f32 %0, %1, %2;" : "=r"(r) : "f"(b), "f"(a));
    return r;
}
__device__ __forceinline__ float bf16_round(float x) {
    return __bfloat162float(__float2bfloat16(x));
}
__device__ __forceinline__ void ldm_x4(uint32_t* r, uint32_t addr) {
    asm volatile("ldmatrix.sync.aligned.m8n8.x4.shared.b16 {%0,%1,%2,%3}, [%4];"
                 : "=r"(r[0]), "=r"(r[1]), "=r"(r[2]), "=r"(r[3]) : "r"(addr));
}
__device__ __forceinline__ void ldm_x2(uint32_t* r, uint32_t addr) {
    asm volatile("ldmatrix.sync.aligned.m8n8.x2.shared.b16 {%0,%1}, [%2];"
                 : "=r"(r[0]), "=r"(r[1]) : "r"(addr));
}
__device__ __forceinline__ void mma_bf16(float* c, const uint32_t* a, const uint32_t* b) {
    asm volatile(
        "mma.sync.aligned.m16n8k16.row.col.f32.bf16.bf16.f32 "
        "{%0,%1,%2,%3},{%4,%5,%6,%7},{%8,%9},{%0,%1,%2,%3};"
        : "+f"(c[0]), "+f"(c[1]), "+f"(c[2]), "+f"(c[3])
        : "r"(a[0]), "r"(a[1]), "r"(a[2]), "r"(a[3]), "r"(b[0]), "r"(b[1]));
}

// ---------------- adjacency dtype detection ----------------
__global__ void detect_kernel(const int* __restrict__ w) {
    if (threadIdx.x == 0) {
        int all0 = 1;
        #pragma unroll 1
        for (int i = 0; i < 64; i++)
            if (w[2 * i + 1] != 0) { all0 = 0; break; }
        g_is64 = all0;
    }
}

// ---------------- CSR build ----------------
__global__ void init_deg_kernel(int n) {
    int i = blockIdx.x * blockDim.x + threadIdx.x;
    if (i < n) g_deg[i] = 1;  // self-loop
}

__global__ void count2_kernel(const int* __restrict__ dst32,
                              const int* __restrict__ dst64, int e) {
    int i = blockIdx.x * blockDim.x + threadIdx.x;
    if (i >= e) return;
    int is64 = g_is64;
    int d = is64 ? dst64[2 * i] : dst32[i];
    atomicAdd(&g_deg[d], 1);
}

#define SCAN_BS 512
__global__ void blockscan_kernel(int n) {
    __shared__ int sh[SCAN_BS];
    int t = threadIdx.x;
    int i = blockIdx.x * SCAN_BS + t;
    int v = (i < n) ? g_deg[i] : 0;
    sh[t] = v;
    __syncthreads();
    #pragma unroll
    for (int d = 1; d < SCAN_BS; d <<= 1) {
        int x = (t >= d) ? sh[t - d] : 0;
        __syncthreads();
        sh[t] += x;
        __syncthreads();
    }
    if (i < n) g_off[i] = sh[t] - v;
    if (t == SCAN_BS - 1) g_bsum[blockIdx.x] = sh[t];
}

__global__ void bsumscan_kernel(int nb, int n) {
    __shared__ int sh[512];
    int t = threadIdx.x;
    int v = (t < nb) ? g_bsum[t] : 0;
    sh[t] = v;
    __syncthreads();
    #pragma unroll
    for (int d = 1; d < 512; d <<= 1) {
        int x = (t >= d) ? sh[t - d] : 0;
        __syncthreads();
        sh[t] += x;
        __syncthreads();
    }
    if (t < nb) g_bsum[t] = sh[t] - v;
    if (t == 511) g_off[n] = sh[511];
}

__global__ void addoff_kernel(int n) {
    int i = blockIdx.x * blockDim.x + threadIdx.x;
    if (i < n) {
        int o = g_off[i] + g_bsum[i >> 9];
        g_off[i] = o;
        g_cur[i] = o;
    }
}

__global__ void scatter2_kernel(const int* __restrict__ src,
                                const int* __restrict__ dst32,
                                const int* __restrict__ dst64, int e, int n) {
    int i = blockIdx.x * blockDim.x + threadIdx.x;
    int is64 = g_is64;
    if (i < e) {
        int d = is64 ? dst64[2 * i] : dst32[i];
        int s = is64 ? src[2 * i] : src[i];
        int p = atomicAdd(&g_cur[d], 1);
        g_srcs[p] = s;
    } else if (i < e + n) {
        int v = i - e;
        int p = atomicAdd(&g_cur[v], 1);
        g_srcs[p] = v;
    }
}

// ---------------- W transpose + bf16 hi/lo split ----------------
__global__ void wsplit_kernel(const float* __restrict__ W, int K, int Nd) {
    int i = blockIdx.x * blockDim.x + threadIdx.x;
    if (i >= K * Nd) return;
    int k = i / Nd, nn = i % Nd;
    float x = W[i];
    float h = bf16_round(x);
    g_Bhi[(size_t)nn * K + k] = __float2bfloat16(h);
    g_Blo[(size_t)nn * K + k] = __float2bfloat16(x - h);
}

// ---------------- mma.sync bf16-split GEMM + fused alpha dots ----------------
// Block: 256 thr (8 warps), tile 128 x NDIM, K-chunk = 64.
// Register double-buffered A AND B staging; epilogue computes g_as/g_ad.
template <int NDIM>
__global__ void __launch_bounds__(256, 2)
mma_gemm_kernel(const float* __restrict__ Ain, int useGX, int M, int K,
                const float* __restrict__ a_src, const float* __restrict__ a_dst) {
    constexpr int ABYTES = 128 * 128;           // 16KB per A tile
    constexpr int BBYTES = NDIM * 128;
    constexpr int NT = NDIM / 8;
    constexpr int BP = NDIM / 16;
    extern __shared__ char smraw[];
    char* smem = (char*)(((uintptr_t)smraw + 1023) & ~(uintptr_t)1023);
    uint32_t aHiB = smem_u32(smem);
    uint32_t aLoB = aHiB + ABYTES;
    uint32_t bHiB = aHiB + 2 * ABYTES;
    uint32_t bLoB = bHiB + BBYTES;

    const float* A = useGX ? g_x : Ain;
    const int tid = threadIdx.x, wid = tid >> 5, lane = tid & 31;
    const int rowBase = blockIdx.x * 128;

    float acc[NT][4];
    #pragma unroll
    for (int nt = 0; nt < NT; nt++)
        #pragma unroll
        for (int q = 0; q < 4; q++) acc[nt][q] = 0.f;

    // per-lane ldmatrix address components
    const int Rw = wid * 16;
    const int aRow = Rw + (lane & 7) + ((lane >> 3) & 1) * 8;
    const uint32_t aRowOff = (uint32_t)aRow * 128;
    const uint32_t aSwz = (uint32_t)(aRow & 7) << 4;
    const uint32_t aHalf = ((lane >> 4) & 1) * 16;
    const uint32_t bRow = (lane & 7);
    const uint32_t bRowOff = bRow * 128;
    const uint32_t bSwz = bRow << 4;
    const uint32_t bHalf = ((lane >> 3) & 1) * 16;

    // staging indices
    const int sr = tid >> 4;            // 0..15
    const int cg = (tid & 15) * 4;      // col group (4 floats)
    const uint32_t stCol = (uint32_t)(cg * 2);

    const int nChunks = K >> 6;

    // ---- register prefetch of chunk 0 (A fp32, B pre-split bf16) ----
    float4 pref[8];
    uint2 prBh[BP], prBl[BP];
    #pragma unroll
    for (int p = 0; p < 8; p++) {
        int gr = rowBase + p * 16 + sr;
        pref[p] = make_float4(0.f, 0.f, 0.f, 0.f);
        if (gr < M)
            pref[p] = *reinterpret_cast<const float4*>(&A[(size_t)gr * K + cg]);
    }
    #pragma unroll
    for (int p = 0; p < BP; p++) {
        int r = p * 16 + sr;
        prBh[p] = *reinterpret_cast<const uint2*>(&g_Bhi[(size_t)r * K + cg]);
        prBl[p] = *reinterpret_cast<const uint2*>(&g_Blo[(size_t)r * K + cg]);
    }

    for (int c = 0; c < nChunks; c++) {
        // ---- store staged A/B (from registers) ----
        #pragma unroll
        for (int p = 0; p < 8; p++) {
            int r = p * 16 + sr;
            float4 v = pref[p];
            float h0 = bf16_round(v.x), h1 = bf16_round(v.y);
            float h2 = bf16_round(v.z), h3 = bf16_round(v.w);
            uint32_t off = (uint32_t)r * 128 + (stCol ^ ((uint32_t)(r & 7) << 4));
            *(uint32_t*)(smem + (off))            = pack_bf16(v.x, v.y);
            *(uint32_t*)(smem + (off + 4))        = pack_bf16(v.z, v.w);
            *(uint32_t*)(smem + ABYTES + off)     = pack_bf16(v.x - h0, v.y - h1);
            *(uint32_t*)(smem + ABYTES + off + 4) = pack_bf16(v.z - h2, v.w - h3);
        }
        #pragma unroll
        for (int p = 0; p < BP; p++) {
            int r = p * 16 + sr;
            uint32_t off = (uint32_t)r * 128 + (stCol ^ ((uint32_t)(r & 7) << 4));
            *(uint32_t*)(smem + 2 * ABYTES + off)              = prBh[p].x;
            *(uint32_t*)(smem + 2 * ABYTES + off + 4)          = prBh[p].y;
            *(uint32_t*)(smem + 2 * ABYTES + BBYTES + off)     = prBl[p].x;
            *(uint32_t*)(smem + 2 * ABYTES + BBYTES + off + 4) = prBl[p].y;
        }
        __syncthreads();

        // ---- prefetch chunk c+1 (overlaps with MMA below) ----
        if (c + 1 < nChunks) {
            const int k1 = (c + 1) << 6;
            #pragma unroll
            for (int p = 0; p < 8; p++) {
                int gr = rowBase + p * 16 + sr;
                pref[p] = make_float4(0.f, 0.f, 0.f, 0.f);
                if (gr < M)
                    pref[p] = *reinterpret_cast<const float4*>(&A[(size_t)gr * K + k1 + cg]);
            }
            #pragma unroll
            for (int p = 0; p < BP; p++) {
                int r = p * 16 + sr;
                prBh[p] = *reinterpret_cast<const uint2*>(&g_Bhi[(size_t)r * K + k1 + cg]);
                prBl[p] = *reinterpret_cast<const uint2*>(&g_Blo[(size_t)r * K + k1 + cg]);
            }
        }

        // ---- compute ----
        #pragma unroll
        for (int kt = 0; kt < 4; kt++) {
            uint32_t aoff = aRowOff + (((uint32_t)kt * 32 + aHalf) ^ aSwz);
            uint32_t ahi[4], alo[4];
            ldm_x4(ahi, aHiB + aoff);
            ldm_x4(alo, aLoB + aoff);
            uint32_t bcol = ((uint32_t)kt * 32 + bHalf) ^ bSwz;
            #pragma unroll
            for (int nt = 0; nt < NT; nt++) {
                uint32_t boff = (uint32_t)nt * 1024 + bRowOff + bcol;
                uint32_t bhi[2], blo[2];
                ldm_x2(bhi, bHiB + boff);
                ldm_x2(blo, bLoB + boff);
                mma_bf16(acc[nt], ahi, bhi);
                mma_bf16(acc[nt], ahi, blo);
                mma_bf16(acc[nt], alo, bhi);
            }
        }
        __syncthreads();
    }

    // ---- epilogue: write h + fused alpha dots ----
    int r0 = rowBase + Rw + (lane >> 2);
    int colb = (lane & 3) * 2;
    float s1p = 0.f, d1p = 0.f, s2p = 0.f, d2p = 0.f;
    #pragma unroll
    for (int nt = 0; nt < NT; nt++) {
        int col = nt * 8 + colb;
        float a0 = a_src[col], a1 = a_src[col + 1];
        float e0 = a_dst[col], e1 = a_dst[col + 1];
        s1p = fmaf(acc[nt][0], a0, fmaf(acc[nt][1], a1, s1p));
        d1p = fmaf(acc[nt][0], e0, fmaf(acc[nt][1], e1, d1p));
        s2p = fmaf(acc[nt][2], a0, fmaf(acc[nt][3], a1, s2p));
        d2p = fmaf(acc[nt][2], e0, fmaf(acc[nt][3], e1, d2p));
        if (r0 < M)
            *reinterpret_cast<float2*>(&g_h[(size_t)r0 * NDIM + col]) =
                make_float2(acc[nt][0], acc[nt][1]);
        if (r0 + 8 < M)
            *reinterpret_cast<float2*>(&g_h[(size_t)(r0 + 8) * NDIM + col]) =
                make_float2(acc[nt][2], acc[nt][3]);
    }
    #pragma unroll
    for (int o = 1; o <= 2; o <<= 1) {
        s1p += __shfl_xor_sync(0xffffffffu, s1p, o);
        d1p += __shfl_xor_sync(0xffffffffu, d1p, o);
        s2p += __shfl_xor_sync(0xffffffffu, s2p, o);
        d2p += __shfl_xor_sync(0xffffffffu, d2p, o);
    }
    if ((lane & 3) == 0) {
        if (r0 < M)     { g_as[r0] = s1p;     g_ad[r0] = d1p; }
        if (r0 + 8 < M) { g_as[r0 + 8] = s2p; g_ad[r0 + 8] = d2p; }
    }
}

// ---------------- segment softmax + aggregation (warp per dst, MLP=2) ----------------
template <int DO, bool TO_GX>
__global__ void aggregate_kernel(const float* __restrict__ bias,
                                 float* __restrict__ outp, int n) {
    constexpr int VEC = DO / 32;
    int node = (blockIdx.x * blockDim.x + threadIdx.x) >> 5;
    int lane = threadIdx.x & 31;
    if (node >= n) return;
    int s0 = g_off[node], s1 = g_off[node + 1];
    float adn = g_ad[node];

    float m = -1e30f;
    for (int j = s0 + lane; j < s1; j += 32) {
        float v = g_as[g_srcs[j]] + adn;
        v = v > 0.f ? v : 0.2f * v;
        m = fmaxf(m, v);
    }
    #pragma unroll
    for (int o = 16; o; o >>= 1) m = fmaxf(m, __shfl_xor_sync(0xffffffffu, m, o));

    float acc[VEC];
    #pragma unroll
    for (int k = 0; k < VEC; k++) acc[k] = 0.f;
    float ssum = 0.f;

    int j = s0;
    const float* hbase = g_h;
    #pragma unroll 1
    for (; j + 2 <= s1; j += 2) {
        int sa = g_srcs[j];
        int sb = g_srcs[j + 1];
        float va = g_as[sa] + adn;
        float vb = g_as[sb] + adn;
        va = va > 0.f ? va : 0.2f * va;
        vb = vb > 0.f ? vb : 0.2f * vb;
        float wa = __expf(va - m);
        float wb = __expf(vb - m);
        ssum += wa + wb;
        if constexpr (VEC == 4) {
            float4 ha = *reinterpret_cast<const float4*>(&hbase[(size_t)sa * DO + lane * 4]);
            float4 hb = *reinterpret_cast<const float4*>(&hbase[(size_t)sb * DO + lane * 4]);
            acc[0] = fmaf(wa, ha.x, fmaf(wb, hb.x, acc[0]));
            acc[1] = fmaf(wa, ha.y, fmaf(wb, hb.y, acc[1]));
            acc[2] = fmaf(wa, ha.z, fmaf(wb, hb.z, acc[2]));
            acc[3] = fmaf(wa, ha.w, fmaf(wb, hb.w, acc[3]));
        } else {
            float2 ha = *reinterpret_cast<const float2*>(&hbase[(size_t)sa * DO + lane * 2]);
            float2 hb = *reinterpret_cast<const float2*>(&hbase[(size_t)sb * DO + lane * 2]);
            acc[0] = fmaf(wa, ha.x, fmaf(wb, hb.x, acc[0]));
            acc[1] = fmaf(wa, ha.y, fmaf(wb, hb.y, acc[1]));
        }
    }
    if (j < s1) {
        int s = g_srcs[j];
        float v = g_as[s] + adn;
        v = v > 0.f ? v : 0.2f * v;
        float w = __expf(v - m);
        ssum += w;
        if constexpr (VEC == 4) {
            float4 hv = *reinterpret_cast<const float4*>(&hbase[(size_t)s * DO + lane * 4]);
            acc[0] = fmaf(w, hv.x, acc[0]);
            acc[1] = fmaf(w, hv.y, acc[1]);
            acc[2] = fmaf(w, hv.z, acc[2]);
            acc[3] = fmaf(w, hv.w, acc[3]);
        } else {
            float2 hv = *reinterpret_cast<const float2*>(&hbase[(size_t)s * DO + lane * 2]);
            acc[0] = fmaf(w, hv.x, acc[0]);
            acc[1] = fmaf(w, hv.y, acc[1]);
        }
    }
    float inv = 1.f / ssum;
    #pragma unroll
    for (int k = 0; k < VEC; k++) {
        float o = fmaf(acc[k], inv, bias[lane * VEC + k]);
        acc[k] = o > 0.f ? o : 0.25f * o;
    }
    float* op = TO_GX ? &g_x[(size_t)node * DO + lane * VEC]
                      : &outp[(size_t)node * DO + lane * VEC];
    if constexpr (VEC == 4)
        *reinterpret_cast<float4*>(op) = make_float4(acc[0], acc[1], acc[2], acc[3]);
    else
        *reinterpret_cast<float2*>(op) = make_float2(acc[0], acc[1]);
}

// ---------------- launch ----------------
extern "C" void kernel_launch(void* const* d_in, const int* in_sizes, int n_in,
                              void* d_out, int out_size) {
    const float* data = (const float*)d_in[0];
    const int*   adj  = (const int*)d_in[1];
    const float* W1  = (const float*)d_in[2];
    const float* as1 = (const float*)d_in[3];
    const float* ad1 = (const float*)d_in[4];
    const float* b1  = (const float*)d_in[5];
    const float* W2  = (const float*)d_in[6];
    const float* as2 = (const float*)d_in[7];
    const float* ad2 = (const float*)d_in[8];
    const float* b2  = (const float*)d_in[9];
    const float* W3  = (const float*)d_in[10];
    const float* as3 = (const float*)d_in[11];
    const float* ad3 = (const float*)d_in[12];
    const float* b3  = (const float*)d_in[13];

    int Nn = in_sizes[0] / 512;
    int Ee = in_sizes[1] / 2;

    // side stream + fork/join events (created once; creation happens on the
    // non-captured correctness call first, reused inside capture afterwards)
    static cudaStream_t s2 = nullptr;
    static cudaEvent_t evFork = nullptr, evJoin = nullptr;
    if (s2 == nullptr) {
        cudaStreamCreateWithFlags(&s2, cudaStreamNonBlocking);
        cudaEventCreateWithFlags(&evFork, cudaEventDisableTiming);
        cudaEventCreateWithFlags(&evJoin, cudaEventDisableTiming);
    }

    const int SM128 = 2 * 128 * 128 + 2 * 128 * 128 + 1024;  // 64KB + pad
    const int SM64  = 2 * 128 * 128 + 2 * 64 * 128 + 1024;   // 48KB + pad
    cudaFuncSetAttribute(mma_gemm_kernel<128>,
                         cudaFuncAttributeMaxDynamicSharedMemorySize, SM128);
    cudaFuncSetAttribute(mma_gemm_kernel<64>,
                         cudaFuncAttributeMaxDynamicSharedMemorySize, SM64);

    const int T = 256;
    int warpGrid = (Nn * 32 + T - 1) / T;
    const int* dst32 = adj + Ee;
    const int* dst64 = adj + 2 * (size_t)Ee;

    // ---- fork: CSR build on side stream, overlapped with wsplit1 + GEMM1 ----
    cudaEventRecord(evFork, 0);
    cudaStreamWaitEvent(s2, evFork, 0);
    detect_kernel<<<1, 32, 0, s2>>>(adj);
    init_deg_kernel<<<(Nn + T - 1) / T, T, 0, s2>>>(Nn);
    count2_kernel<<<(Ee + T - 1) / T, T, 0, s2>>>(dst32, dst64, Ee);
    int nb = (Nn + SCAN_BS - 1) / SCAN_BS;
    blockscan_kernel<<<nb, SCAN_BS, 0, s2>>>(Nn);
    bsumscan_kernel<<<1, 512, 0, s2>>>(nb, Nn);
    addoff_kernel<<<(Nn + T - 1) / T, T, 0, s2>>>(Nn);
    scatter2_kernel<<<(Ee + Nn + T - 1) / T, T, 0, s2>>>(adj, dst32, dst64, Ee, Nn);
    cudaEventRecord(evJoin, s2);

    int gBlocks = (Nn + 127) / 128;

    // layer 1: K=512 -> 128 (independent of CSR)
    wsplit_kernel<<<(512 * 128 + T - 1) / T, T>>>(W1, 512, 128);
    mma_gemm_kernel<128><<<gBlocks, 256, SM128>>>(data, 0, Nn, 512, as1, ad1);
    cudaStreamWaitEvent(0, evJoin, 0);   // join before first aggregation
    aggregate_kernel<128, true><<<warpGrid, T>>>(b1, nullptr, Nn);

    // layer 2: K=128 -> 128
    wsplit_kernel<<<(128 * 128 + T - 1) / T, T>>>(W2, 128, 128);
    mma_gemm_kernel<128><<<gBlocks, 256, SM128>>>(nullptr, 1, Nn, 128, as2, ad2);
    aggregate_kernel<128, true><<<warpGrid, T>>>(b2, nullptr, Nn);

    // layer 3: K=128 -> 64
    wsplit_kernel<<<(128 * 64 + T - 1) / T, T>>>(W3, 128, 64);
    mma_gemm_kernel<64><<<gBlocks, 256, SM64>>>(nullptr, 1, Nn, 128, as3, ad3);
    aggregate_kernel<64, false><<<warpGrid, T>>>(b3, (float*)d_out, Nn);
}